// round 3
// baseline (speedup 1.0000x reference)
#include <cuda_runtime.h>
#include <cstdint>

#define BB 16
#define NN 4096
#define DD 1024
#define HH 16
#define DKK 64
#define NCHUNK 32          // n-split for weighted-sum partials
#define RPB 64             // rows per block in scores kernel
#define RPC (NN / NCHUNK)  // 128 rows per chunk in wsum kernel

// ---- scratch (static __device__ — no allocation allowed) ----
__device__ float g_qk[HH * DD];                                // folded (log2e/SCALE) * Q@Wk_head
__device__ float g_e[(size_t)BB * NN * HH];                    // exp2(score*log2e/SCALE), [b][n][h]
__device__ float g_ps[(size_t)BB * NCHUNK * HH * DD];          // partial weighted sums (32 MB)
__device__ float g_pz[BB * NCHUNK * HH];                       // partial softmax denominators
__device__ float g_z[BB * HH];                                 // total denominators
__device__ float g_s[(size_t)BB * HH * DD];                    // normalized weighted avg of x
__device__ float g_pooled[BB * DD];                            // per-head Wv matvec results

// ---------------------------------------------------------------------------
// K0: qk[h][d] = (log2e/SCALE) * sum_j query[h][j] * Wk[h*64+j][d]
// one thread per (h,d); 64 blocks x 256 threads
// ---------------------------------------------------------------------------
__global__ void k0_qk(const float* __restrict__ Wk, const float* __restrict__ query) {
    int gid = blockIdx.x * 256 + threadIdx.x;   // 16384 = H*D
    int h = gid >> 10;
    int d = gid & 1023;
    const float C = 0.125f * 1.4426950408889634f;   // (1/SCALE) * log2(e)
    float acc = 0.f;
#pragma unroll 8
    for (int j = 0; j < DKK; j++) {
        acc += __ldg(&query[h * DKK + j]) * __ldg(&Wk[(size_t)(h * DKK + j) * DD + d]);
    }
    g_qk[gid] = acc * C;
}

// ---------------------------------------------------------------------------
// K1: scores -> e[b][n][h] = exp2(x[b,n,:] . qk[h,:])
// block = 128 threads = 4 warps; warp w owns heads 4w..4w+3 with qk in REGISTERS
// (32 float4 per lane). All warps sweep the same rows -> x hits L1 after warp 0.
// grid = B*N/RPB = 1024 blocks
// ---------------------------------------------------------------------------
__global__ void __launch_bounds__(128) k1_scores(const float* __restrict__ x) {
    int w = threadIdx.x >> 5;
    int l = threadIdx.x & 31;

    // lane l covers d = 4l + 128*i, i<8 ; per head 8 float4 = 32 floats
    float4 qkr[4][8];
#pragma unroll
    for (int h = 0; h < 4; h++) {
#pragma unroll
        for (int i = 0; i < 8; i++) {
            qkr[h][i] = *(const float4*)&g_qk[(4 * w + h) * DD + 4 * l + 128 * i];
        }
    }

    size_t r0 = (size_t)blockIdx.x * RPB;
    for (int rr = 0; rr < RPB; rr++) {
        size_t r = r0 + rr;
        const float4* xr = (const float4*)(x + r * DD);
        float a0 = 0.f, a1 = 0.f, a2 = 0.f, a3 = 0.f;
#pragma unroll
        for (int i = 0; i < 8; i++) {
            float4 x4 = __ldg(&xr[l + 32 * i]);
            a0 += x4.x * qkr[0][i].x + x4.y * qkr[0][i].y + x4.z * qkr[0][i].z + x4.w * qkr[0][i].w;
            a1 += x4.x * qkr[1][i].x + x4.y * qkr[1][i].y + x4.z * qkr[1][i].z + x4.w * qkr[1][i].w;
            a2 += x4.x * qkr[2][i].x + x4.y * qkr[2][i].y + x4.z * qkr[2][i].z + x4.w * qkr[2][i].w;
            a3 += x4.x * qkr[3][i].x + x4.y * qkr[3][i].y + x4.z * qkr[3][i].z + x4.w * qkr[3][i].w;
        }
        float a[4] = {a0, a1, a2, a3};
#pragma unroll
        for (int h = 0; h < 4; h++) {
            float v = a[h];
            v += __shfl_xor_sync(0xffffffffu, v, 16);
            v += __shfl_xor_sync(0xffffffffu, v, 8);
            v += __shfl_xor_sync(0xffffffffu, v, 4);
            v += __shfl_xor_sync(0xffffffffu, v, 2);
            v += __shfl_xor_sync(0xffffffffu, v, 1);
            if (l == h) g_e[r * HH + 4 * w + h] = exp2f(v);
        }
    }
}

// ---------------------------------------------------------------------------
// K2: partial weighted sums. Block (c, b): rows n in [c*128, c*128+128),
// 256 threads, thread t owns columns 4t..4t+3 (full D covered).
// Per row: 1 LDG128 (x), 4 LDS128 (e broadcast), 64 FMA.
// Writes partial s (16 heads x 4 cols) and partial z to scratch.
// ---------------------------------------------------------------------------
__global__ void __launch_bounds__(256) k2_wsum(const float* __restrict__ x) {
    int c = blockIdx.x;
    int b = blockIdx.y;
    int t = threadIdx.x;

    __shared__ float es[RPC][HH];   // 8 KB
    int n0 = c * RPC;
    const float* esrc = &g_e[((size_t)b * NN + n0) * HH];
    for (int idx = t; idx < RPC * HH; idx += 256) {
        es[idx >> 4][idx & 15] = esrc[idx];
    }
    __syncthreads();

    float4 acc[HH];
#pragma unroll
    for (int h = 0; h < HH; h++) acc[h] = make_float4(0.f, 0.f, 0.f, 0.f);

    const float4* xb = (const float4*)(x + ((size_t)b * NN + n0) * DD);
    for (int r = 0; r < RPC; r++) {
        float4 x4 = __ldg(&xb[(size_t)r * (DD / 4) + t]);
        const float4* er = (const float4*)es[r];
        float4 e0 = er[0], e1 = er[1], e2 = er[2], e3 = er[3];
        float ev[16] = {e0.x, e0.y, e0.z, e0.w, e1.x, e1.y, e1.z, e1.w,
                        e2.x, e2.y, e2.z, e2.w, e3.x, e3.y, e3.z, e3.w};
#pragma unroll
        for (int h = 0; h < HH; h++) {
            acc[h].x += x4.x * ev[h];
            acc[h].y += x4.y * ev[h];
            acc[h].z += x4.z * ev[h];
            acc[h].w += x4.w * ev[h];
        }
    }

    size_t base = (size_t)(b * NCHUNK + c) * HH * DD;
#pragma unroll
    for (int h = 0; h < HH; h++) {
        *(float4*)&g_ps[base + (size_t)h * DD + 4 * t] = acc[h];
    }

    if (t < HH) {
        float z = 0.f;
        for (int r = 0; r < RPC; r++) z += es[r][t];
        g_pz[(b * NCHUNK + c) * HH + t] = z;
    }
}

// ---------------------------------------------------------------------------
// KZ: total denominators. 1 block, 256 threads = B*H entries.
// ---------------------------------------------------------------------------
__global__ void kz_total() {
    int t = threadIdx.x;
    int b = t >> 4, h = t & 15;
    float z = 0.f;
#pragma unroll
    for (int c = 0; c < NCHUNK; c++) z += g_pz[(b * NCHUNK + c) * HH + h];
    g_z[t] = z;
}

// ---------------------------------------------------------------------------
// K3: combine partials + normalize: s[b][h][d] = sum_c ps / z[b][h]
// 1024 blocks x 256 threads over B*H*D = 262144
// ---------------------------------------------------------------------------
__global__ void k3_combine() {
    size_t gid = (size_t)blockIdx.x * 256 + threadIdx.x;
    int b = (int)(gid >> 14);
    int rem = (int)(gid & 16383);          // h*1024 + d
    float sum = 0.f;
#pragma unroll
    for (int c = 0; c < NCHUNK; c++) {
        sum += g_ps[(size_t)(b * NCHUNK + c) * HH * DD + rem];
    }
    g_s[gid] = sum / g_z[gid >> 10];       // gid>>10 == b*16+h
}

// ---------------------------------------------------------------------------
// K4: pooled[b][o] = Wv[o,:] . s[b][o>>6][:]   (o = h*64+j)
// warp per output; grid (128, B), 8 warps/block
// ---------------------------------------------------------------------------
__global__ void __launch_bounds__(256) k4_pooled(const float* __restrict__ Wv) {
    int w = threadIdx.x >> 5, l = threadIdx.x & 31;
    int o = blockIdx.x * 8 + w;
    int b = blockIdx.y;
    int h = o >> 6;
    const float4* wr = (const float4*)(Wv + (size_t)o * DD);
    const float4* sr = (const float4*)(g_s + (size_t)(b * HH + h) * DD);
    float acc = 0.f;
#pragma unroll
    for (int i = 0; i < 8; i++) {
        float4 a = __ldg(&wr[l + 32 * i]);
        float4 s4 = sr[l + 32 * i];
        acc += a.x * s4.x + a.y * s4.y + a.z * s4.z + a.w * s4.w;
    }
    acc += __shfl_xor_sync(0xffffffffu, acc, 16);
    acc += __shfl_xor_sync(0xffffffffu, acc, 8);
    acc += __shfl_xor_sync(0xffffffffu, acc, 4);
    acc += __shfl_xor_sync(0xffffffffu, acc, 2);
    acc += __shfl_xor_sync(0xffffffffu, acc, 1);
    if (l == 0) g_pooled[b * DD + o] = acc;
}

// ---------------------------------------------------------------------------
// K5: out[b][i] = Wout[i,:] . pooled[b,:] + bout[i]
// ---------------------------------------------------------------------------
__global__ void __launch_bounds__(256) k5_out(const float* __restrict__ Wout,
                                              const float* __restrict__ bout,
                                              float* __restrict__ out) {
    int w = threadIdx.x >> 5, l = threadIdx.x & 31;
    int i = blockIdx.x * 8 + w;
    int b = blockIdx.y;
    const float4* wr = (const float4*)(Wout + (size_t)i * DD);
    const float4* pr = (const float4*)(g_pooled + (size_t)b * DD);
    float acc = 0.f;
#pragma unroll
    for (int k = 0; k < 8; k++) {
        float4 a = __ldg(&wr[l + 32 * k]);
        float4 p4 = pr[l + 32 * k];
        acc += a.x * p4.x + a.y * p4.y + a.z * p4.z + a.w * p4.w;
    }
    acc += __shfl_xor_sync(0xffffffffu, acc, 16);
    acc += __shfl_xor_sync(0xffffffffu, acc, 8);
    acc += __shfl_xor_sync(0xffffffffu, acc, 4);
    acc += __shfl_xor_sync(0xffffffffu, acc, 2);
    acc += __shfl_xor_sync(0xffffffffu, acc, 1);
    if (l == 0) out[b * DD + i] = acc + __ldg(&bout[i]);
}

// ---------------------------------------------------------------------------
extern "C" void kernel_launch(void* const* d_in, const int* in_sizes, int n_in,
                              void* d_out, int out_size) {
    const float* x     = (const float*)d_in[0];  // (16,4096,1024)
    const float* Wk    = (const float*)d_in[1];  // (1024,1024)
    const float* Wv    = (const float*)d_in[2];  // (1024,1024)
    const float* query = (const float*)d_in[3];  // (16,1,64)
    const float* Wout  = (const float*)d_in[4];  // (1024,1024)
    const float* bout  = (const float*)d_in[5];  // (1024,)
    float* out = (float*)d_out;                  // (16,1024)

    k0_qk<<<HH * DD / 256, 256>>>(Wk, query);
    k1_scores<<<BB * NN / RPB, 128>>>(x);
    k2_wsum<<<dim3(NCHUNK, BB), 256>>>(x);
    kz_total<<<1, 256>>>();
    k3_combine<<<BB * HH * DD / 256, 256>>>();
    k4_pooled<<<dim3(DD / 8, BB), 256>>>(Wv);
    k5_out<<<dim3(DD / 8, BB), 256>>>(Wout, bout, out);
}

// round 4
// speedup vs baseline: 1.3411x; 1.3411x over previous
#include <cuda_runtime.h>
#include <cstdint>

#define BB 16
#define NN 4096
#define DD 1024
#define HH 16
#define DKK 64
#define CBLK 9            // row-chunks per batch (144 blocks total ~= 1 wave)
#define RPBK 456          // rows per block (last block gets 448; both /8)
#define TR 8              // tile rows

typedef unsigned long long u64;

// ---- scratch (static __device__ — no allocation allowed) ----
__device__ float g_qk[HH * DD];                          // folded (log2e/SCALE) * Q@Wk_head
__device__ float g_ps[(size_t)BB * CBLK * HH * DD];      // partial weighted sums (9.4 MB)
__device__ float g_pz[BB * CBLK * HH];                   // partial softmax denominators
__device__ float g_z[BB * HH];                           // total denominators
__device__ float g_s[(size_t)BB * HH * DD];              // normalized weighted avg of x
__device__ float g_pooled[BB * DD];                      // per-head Wv matvec results

// ---- packed f32x2 helpers (FFMA2 only reachable via PTX on sm_103a) ----
__device__ __forceinline__ u64 ffma2(u64 a, u64 b, u64 c) {
    u64 d;
    asm("fma.rn.f32x2 %0, %1, %2, %3;" : "=l"(d) : "l"(a), "l"(b), "l"(c));
    return d;
}
__device__ __forceinline__ u64 pack2(float lo, float hi) {
    u64 d;
    asm("mov.b64 %0, {%1, %2};" : "=l"(d) : "f"(lo), "f"(hi));
    return d;
}
__device__ __forceinline__ float2 unpack2(u64 v) {
    float2 r;
    asm("mov.b64 {%0, %1}, %2;" : "=f"(r.x), "=f"(r.y) : "l"(v));
    return r;
}

// ---------------------------------------------------------------------------
// K0: qk[h][d] = (log2e/SCALE) * sum_j query[h][j] * Wk[h*64+j][d]
// ---------------------------------------------------------------------------
__global__ void k0_qk(const float* __restrict__ Wk, const float* __restrict__ query) {
    int gid = blockIdx.x * 256 + threadIdx.x;   // 16384 = H*D
    int h = gid >> 10;
    int d = gid & 1023;
    const float C = 0.125f * 1.4426950408889634f;   // (1/SCALE) * log2(e)
    float acc = 0.f;
#pragma unroll 8
    for (int j = 0; j < DKK; j++) {
        acc += __ldg(&query[h * DKK + j]) * __ldg(&Wk[(size_t)(h * DKK + j) * DD + d]);
    }
    g_qk[gid] = acc * C;
}

// ---------------------------------------------------------------------------
// FUSED: per 8-row tile —
//   Phase A: warp (hg = w&3, p = w>>2) computes heads 4hg..4hg+3 for rows
//            r = p,p+2,p+4,p+6 ; qk in registers as f32x2 pairs ; packed dot
//            over d ; butterfly reduce ; exp2 -> es[r][h] in smem.
//   Phase B: thread t owns cols 4t..4t+3 of every row; head-packed FFMA2:
//            acc{2h,2h+1}[c] += {e_2h,e_2h+1} * {x_c,x_c}. x re-read from L1.
// Epilogue: coalesced float4 partial writes + partial z.
// ---------------------------------------------------------------------------
__global__ void __launch_bounds__(256) fused_attn(const float* __restrict__ x) {
    int c = blockIdx.x;           // row chunk within batch
    int b = blockIdx.y;           // batch
    int t = threadIdx.x;
    int w = t >> 5, l = t & 31;
    int hg = w & 3, p = w >> 2;

    __shared__ __align__(16) float es[TR][HH];   // 512 B

    // qk for my 4 heads, lane l covers d = 4l + 128*i (i<8), as f32x2 pairs
    u64 qkr[4][16];
#pragma unroll
    for (int h = 0; h < 4; h++) {
        const ulonglong2* q = (const ulonglong2*)&g_qk[(4 * hg + h) * DD + 4 * l];
#pragma unroll
        for (int i = 0; i < 8; i++) {
            ulonglong2 v = q[32 * i];
            qkr[h][2 * i] = v.x;
            qkr[h][2 * i + 1] = v.y;
        }
    }

    // head-pair packed accumulators: acc[hp][c] holds {head 2hp, head 2hp+1}
    u64 acc[8][4];
#pragma unroll
    for (int hp = 0; hp < 8; hp++)
#pragma unroll
        for (int cc = 0; cc < 4; cc++) acc[hp][cc] = 0ull;

    float zacc = 0.f;

    int n0 = c * RPBK;
    int nrows = NN - n0; if (nrows > RPBK) nrows = RPBK;
    int ntiles = nrows / TR;

    const float* xb = x + ((size_t)b * NN + n0) * DD;

    for (int tile = 0; tile < ntiles; tile++) {
        const float* xt = xb + (size_t)tile * TR * DD;

        // ---- Phase A: scores for my (rows, heads) ----
#pragma unroll
        for (int j = 0; j < 4; j++) {
            int r = p + 2 * j;
            const ulonglong2* xr = (const ulonglong2*)(xt + (size_t)r * DD);
            u64 a0 = 0ull, a1 = 0ull, a2 = 0ull, a3 = 0ull;
#pragma unroll
            for (int i = 0; i < 8; i++) {
                ulonglong2 xv = __ldg(&xr[l + 32 * i]);
                a0 = ffma2(xv.x, qkr[0][2 * i], a0);
                a1 = ffma2(xv.x, qkr[1][2 * i], a1);
                a2 = ffma2(xv.x, qkr[2][2 * i], a2);
                a3 = ffma2(xv.x, qkr[3][2 * i], a3);
                a0 = ffma2(xv.y, qkr[0][2 * i + 1], a0);
                a1 = ffma2(xv.y, qkr[1][2 * i + 1], a1);
                a2 = ffma2(xv.y, qkr[2][2 * i + 1], a2);
                a3 = ffma2(xv.y, qkr[3][2 * i + 1], a3);
            }
            float2 f0 = unpack2(a0), f1 = unpack2(a1), f2v = unpack2(a2), f3 = unpack2(a3);
            float s0 = f0.x + f0.y, s1 = f1.x + f1.y, s2 = f2v.x + f2v.y, s3 = f3.x + f3.y;
#pragma unroll
            for (int m = 16; m > 0; m >>= 1) {
                s0 += __shfl_xor_sync(0xffffffffu, s0, m);
                s1 += __shfl_xor_sync(0xffffffffu, s1, m);
                s2 += __shfl_xor_sync(0xffffffffu, s2, m);
                s3 += __shfl_xor_sync(0xffffffffu, s3, m);
            }
            if (l == 0)      es[r][4 * hg + 0] = exp2f(s0);
            else if (l == 1) es[r][4 * hg + 1] = exp2f(s1);
            else if (l == 2) es[r][4 * hg + 2] = exp2f(s2);
            else if (l == 3) es[r][4 * hg + 3] = exp2f(s3);
        }
        __syncthreads();

        // ---- Phase B: head-packed weighted accumulation, x from L1 ----
#pragma unroll
        for (int r = 0; r < TR; r++) {
            float4 x4 = __ldg((const float4*)(xt + (size_t)r * DD) + t);
            u64 xc0 = pack2(x4.x, x4.x);
            u64 xc1 = pack2(x4.y, x4.y);
            u64 xc2 = pack2(x4.z, x4.z);
            u64 xc3 = pack2(x4.w, x4.w);
            const ulonglong2* ep = (const ulonglong2*)es[r];
            ulonglong2 e0 = ep[0], e1 = ep[1], e2 = ep[2], e3 = ep[3];
            u64 eh[8] = {e0.x, e0.y, e1.x, e1.y, e2.x, e2.y, e3.x, e3.y};
#pragma unroll
            for (int hp = 0; hp < 8; hp++) {
                acc[hp][0] = ffma2(eh[hp], xc0, acc[hp][0]);
                acc[hp][1] = ffma2(eh[hp], xc1, acc[hp][1]);
                acc[hp][2] = ffma2(eh[hp], xc2, acc[hp][2]);
                acc[hp][3] = ffma2(eh[hp], xc3, acc[hp][3]);
            }
        }
        if (t < HH) {
#pragma unroll
            for (int r = 0; r < TR; r++) zacc += es[r][t];
        }
        __syncthreads();
    }

    // ---- epilogue: coalesced partial writes ----
    size_t base = (size_t)(b * CBLK + c) * HH * DD;
#pragma unroll
    for (int hp = 0; hp < 8; hp++) {
        float2 v0 = unpack2(acc[hp][0]);
        float2 v1 = unpack2(acc[hp][1]);
        float2 v2 = unpack2(acc[hp][2]);
        float2 v3 = unpack2(acc[hp][3]);
        float4 lo = make_float4(v0.x, v1.x, v2.x, v3.x);   // head 2hp
        float4 hi = make_float4(v0.y, v1.y, v2.y, v3.y);   // head 2hp+1
        *(float4*)&g_ps[base + (size_t)(2 * hp) * DD + 4 * t] = lo;
        *(float4*)&g_ps[base + (size_t)(2 * hp + 1) * DD + 4 * t] = hi;
    }
    if (t < HH) g_pz[(b * CBLK + c) * HH + t] = zacc;
}

// ---------------------------------------------------------------------------
// KZ: total denominators. 1 block, 256 threads = B*H entries.
// ---------------------------------------------------------------------------
__global__ void kz_total() {
    int t = threadIdx.x;
    int b = t >> 4, h = t & 15;
    float z = 0.f;
#pragma unroll
    for (int c = 0; c < CBLK; c++) z += g_pz[(b * CBLK + c) * HH + h];
    g_z[t] = z;
}

// ---------------------------------------------------------------------------
// K3: combine partials + normalize: s[b][h][d] = sum_c ps / z[b][h]
// ---------------------------------------------------------------------------
__global__ void k3_combine() {
    size_t gid = (size_t)blockIdx.x * 256 + threadIdx.x;   // B*H*D = 262144
    int b = (int)(gid >> 14);
    int rem = (int)(gid & 16383);          // h*1024 + d
    float sum = 0.f;
#pragma unroll
    for (int c = 0; c < CBLK; c++) {
        sum += g_ps[(size_t)(b * CBLK + c) * HH * DD + rem];
    }
    g_s[gid] = sum / g_z[gid >> 10];       // gid>>10 == b*16+h
}

// ---------------------------------------------------------------------------
// K4: pooled[b][o] = Wv[o,:] . s[b][o>>6][:]
// ---------------------------------------------------------------------------
__global__ void __launch_bounds__(256) k4_pooled(const float* __restrict__ Wv) {
    int w = threadIdx.x >> 5, l = threadIdx.x & 31;
    int o = blockIdx.x * 8 + w;
    int b = blockIdx.y;
    int h = o >> 6;
    const float4* wr = (const float4*)(Wv + (size_t)o * DD);
    const float4* sr = (const float4*)(g_s + (size_t)(b * HH + h) * DD);
    float acc = 0.f;
#pragma unroll
    for (int i = 0; i < 8; i++) {
        float4 a = __ldg(&wr[l + 32 * i]);
        float4 s4 = sr[l + 32 * i];
        acc += a.x * s4.x + a.y * s4.y + a.z * s4.z + a.w * s4.w;
    }
    acc += __shfl_xor_sync(0xffffffffu, acc, 16);
    acc += __shfl_xor_sync(0xffffffffu, acc, 8);
    acc += __shfl_xor_sync(0xffffffffu, acc, 4);
    acc += __shfl_xor_sync(0xffffffffu, acc, 2);
    acc += __shfl_xor_sync(0xffffffffu, acc, 1);
    if (l == 0) g_pooled[b * DD + o] = acc;
}

// ---------------------------------------------------------------------------
// K5: out[b][i] = Wout[i,:] . pooled[b,:] + bout[i]
// ---------------------------------------------------------------------------
__global__ void __launch_bounds__(256) k5_out(const float* __restrict__ Wout,
                                              const float* __restrict__ bout,
                                              float* __restrict__ out) {
    int w = threadIdx.x >> 5, l = threadIdx.x & 31;
    int i = blockIdx.x * 8 + w;
    int b = blockIdx.y;
    const float4* wr = (const float4*)(Wout + (size_t)i * DD);
    const float4* pr = (const float4*)(g_pooled + (size_t)b * DD);
    float acc = 0.f;
#pragma unroll
    for (int k = 0; k < 8; k++) {
        float4 a = __ldg(&wr[l + 32 * k]);
        float4 p4 = pr[l + 32 * k];
        acc += a.x * p4.x + a.y * p4.y + a.z * p4.z + a.w * p4.w;
    }
    acc += __shfl_xor_sync(0xffffffffu, acc, 16);
    acc += __shfl_xor_sync(0xffffffffu, acc, 8);
    acc += __shfl_xor_sync(0xffffffffu, acc, 4);
    acc += __shfl_xor_sync(0xffffffffu, acc, 2);
    acc += __shfl_xor_sync(0xffffffffu, acc, 1);
    if (l == 0) out[b * DD + i] = acc + __ldg(&bout[i]);
}

// ---------------------------------------------------------------------------
extern "C" void kernel_launch(void* const* d_in, const int* in_sizes, int n_in,
                              void* d_out, int out_size) {
    const float* x     = (const float*)d_in[0];  // (16,4096,1024)
    const float* Wk    = (const float*)d_in[1];  // (1024,1024)
    const float* Wv    = (const float*)d_in[2];  // (1024,1024)
    const float* query = (const float*)d_in[3];  // (16,1,64)
    const float* Wout  = (const float*)d_in[4];  // (1024,1024)
    const float* bout  = (const float*)d_in[5];  // (1024,)
    float* out = (float*)d_out;                  // (16,1024)

    k0_qk<<<HH * DD / 256, 256>>>(Wk, query);
    fused_attn<<<dim3(CBLK, BB), 256>>>(x);
    kz_total<<<1, 256>>>();
    k3_combine<<<BB * HH * DD / 256, 256>>>();
    k4_pooled<<<dim3(DD / 8, BB), 256>>>(Wv);
    k5_out<<<dim3(DD / 8, BB), 256>>>(Wout, bout, out);
}